// round 3
// baseline (speedup 1.0000x reference)
#include <cuda_runtime.h>
#include <cuda_bf16.h>
#include <cstdint>

// Problem constants
#define B_     8
#define CIN_   512
#define COUT_  512
#define WDIM_  512
#define H_     64
#define W_     64
#define HW_    (H_ * W_)

// Scratch (device globals — no allocation allowed)
__device__ float g_s[B_ * CIN_];       // style s
__device__ float g_ssq[B_ * CIN_];     // s^2
__device__ float g_wsqT[CIN_ * COUT_]; // sum_kk weight^2, transposed [cin][cout]
__device__ float g_d[B_ * COUT_];      // demod rsqrt

// ---------------------------------------------------------------------------
// Kernel 1: style  s[b][c] = sum_d w[b][d]*affine_w[c][d] + affine_b[c] + 1
// grid(B_), block(CIN_)
// ---------------------------------------------------------------------------
__global__ void style_kernel(const float* __restrict__ w,
                             const float* __restrict__ aw,
                             const float* __restrict__ ab) {
    int b = blockIdx.x;
    int c = threadIdx.x;
    __shared__ float wsh[WDIM_];
    wsh[c] = w[b * WDIM_ + c];
    __syncthreads();
    const float* awr = aw + (size_t)c * WDIM_;
    float acc = 0.f;
#pragma unroll 8
    for (int d = 0; d < WDIM_; ++d) acc += awr[d] * wsh[d];
    float s = acc + ab[c] + 1.0f;
    g_s[b * CIN_ + c] = s;
    g_ssq[b * CIN_ + c] = s * s;
}

// ---------------------------------------------------------------------------
// Kernel 2: wsqT[cin][cout] = sum_tap weight[cout][cin][tap]^2
// ---------------------------------------------------------------------------
__global__ void wsq_kernel(const float* __restrict__ weight) {
    int idx = blockIdx.x * blockDim.x + threadIdx.x; // co*512 + cin
    if (idx >= COUT_ * CIN_) return;
    int co = idx >> 9;
    int cin = idx & 511;
    const float* wp = weight + (size_t)idx * 9;
    float s = 0.f;
#pragma unroll
    for (int t = 0; t < 9; ++t) s += wp[t] * wp[t];
    g_wsqT[cin * COUT_ + co] = s;
}

// ---------------------------------------------------------------------------
// Kernel 3: demod d[b][co] = rsqrt( sum_cin ssq[b][cin]*wsqT[cin][co] + 1e-8 )
// ---------------------------------------------------------------------------
__global__ void demod_kernel() {
    int b = blockIdx.x;
    int co = threadIdx.x;
    __shared__ float sq[CIN_];
    sq[co] = g_ssq[b * CIN_ + co];
    __syncthreads();
    float acc = 1e-8f;
#pragma unroll 8
    for (int ci = 0; ci < CIN_; ++ci)
        acc += sq[ci] * g_wsqT[ci * COUT_ + co];
    g_d[b * COUT_ + co] = rsqrtf(acc);
}

// ---------------------------------------------------------------------------
// Kernel 4: main conv + epilogue
//   y[b,co,h,w] = leaky( d[b,co] * sum_{cin,ky,kx} (x[b,cin,h+ky-1,w+kx-1]*s[b,cin])
//                                  * W[co,cin,ky,kx]  + noise + bias[co] )
// Block: 64 cout x (16 rows x 8 cols) pixels, 256 threads.
// Thread (row = t&15, co_sub = t>>4): 4 co (co_sub + 16*i) x 8-pixel row.
// ---------------------------------------------------------------------------
#define CHUNK 16
#define COT   64   // cout tile
#define RT    16   // row tile
#define CT    8    // col tile

__global__ __launch_bounds__(256, 2)
void modconv_kernel(const float* __restrict__ x,
                    const float* __restrict__ weight,
                    const float* __restrict__ noise,
                    const float* __restrict__ bias,
                    float* __restrict__ out) {
    __shared__ float xs[CHUNK][RT + 2][10];   // 16*18*10 floats = 11.25 KB
    __shared__ float ws2[COT][CHUNK * 9 + 1]; // [64][145]      = 36.25 KB

    const int t = threadIdx.x;
    const int row = t & 15;      // 0..15
    const int co_sub = t >> 4;   // 0..15
    const int b = blockIdx.z;
    const int co0 = blockIdx.x * COT;
    const int tile = blockIdx.y;            // 0..31
    const int h0 = (tile >> 3) * RT;        // 4 row tiles of 16
    const int w0 = (tile & 7) * CT;         // 8 col tiles of 8

    const float* xb = x + (size_t)b * CIN_ * HW_;
    const float* sb = g_s + b * CIN_;

    float acc[4][8];
#pragma unroll
    for (int i = 0; i < 4; ++i)
#pragma unroll
        for (int j = 0; j < 8; ++j) acc[i][j] = 0.f;

    for (int cin0 = 0; cin0 < CIN_; cin0 += CHUNK) {
        __syncthreads();
        // ---- load x tile (with halo + per-cin modulation) ----
        for (int e = t; e < CHUNK * (RT + 2) * 10; e += 256) {
            int c = e / ((RT + 2) * 10);
            int r = (e / 10) % (RT + 2);
            int cc = e % 10;
            int h = h0 + r - 1;
            int w = w0 + cc - 1;
            float v = 0.f;
            if (h >= 0 && h < H_ && w >= 0 && w < W_)
                v = xb[(cin0 + c) * HW_ + h * W_ + w] * sb[cin0 + c];
            xs[c][r][cc] = v;
        }
        // ---- load weight tile: ws2[col][c*9+tap] ----
        const float* wg = weight + ((size_t)co0 * CIN_ + cin0) * 9;
        for (int e = t; e < COT * CHUNK * 9; e += 256) {
            int col = e / (CHUNK * 9);
            int q = e % (CHUNK * 9);
            ws2[col][q] = wg[(size_t)col * (CIN_ * 9) + q];
        }
        __syncthreads();
        // ---- compute ----
#pragma unroll 2
        for (int c = 0; c < CHUNK; ++c) {
#pragma unroll
            for (int ky = 0; ky < 3; ++ky) {
                const int qb = c * 9 + ky * 3;
                float xv[10];
#pragma unroll
                for (int q = 0; q < 10; ++q) xv[q] = xs[c][row + ky][q];
#pragma unroll
                for (int i = 0; i < 4; ++i) {
                    const int col = co_sub + 16 * i;
                    const float wv0 = ws2[col][qb + 0];
                    const float wv1 = ws2[col][qb + 1];
                    const float wv2 = ws2[col][qb + 2];
#pragma unroll
                    for (int j = 0; j < 8; ++j) {
                        acc[i][j] += wv0 * xv[j];
                        acc[i][j] += wv1 * xv[j + 1];
                        acc[i][j] += wv2 * xv[j + 2];
                    }
                }
            }
        }
    }

    // ---- epilogue: demod, noise, bias, leaky relu ----
    const int h = h0 + row;
#pragma unroll
    for (int i = 0; i < 4; ++i) {
        const int co = co0 + co_sub + 16 * i;
        const float dd = g_d[b * COUT_ + co];
        const float bs = bias[co];
        const size_t base = ((size_t)(b * COUT_ + co) * H_ + h) * W_ + w0;
        const float4 n0 = *(const float4*)(noise + base);
        const float4 n1 = *(const float4*)(noise + base + 4);
        float r[8];
        r[0] = dd * acc[i][0] + n0.x + bs;
        r[1] = dd * acc[i][1] + n0.y + bs;
        r[2] = dd * acc[i][2] + n0.z + bs;
        r[3] = dd * acc[i][3] + n0.w + bs;
        r[4] = dd * acc[i][4] + n1.x + bs;
        r[5] = dd * acc[i][5] + n1.y + bs;
        r[6] = dd * acc[i][6] + n1.z + bs;
        r[7] = dd * acc[i][7] + n1.w + bs;
#pragma unroll
        for (int j = 0; j < 8; ++j) r[j] = r[j] >= 0.f ? r[j] : 0.2f * r[j];
        *(float4*)(out + base) = make_float4(r[0], r[1], r[2], r[3]);
        *(float4*)(out + base + 4) = make_float4(r[4], r[5], r[6], r[7]);
    }
}

// ---------------------------------------------------------------------------
// Launch
// Inputs (metadata order): x, w, noise, weight, affine_w, affine_b, bias
// ---------------------------------------------------------------------------
extern "C" void kernel_launch(void* const* d_in, const int* in_sizes, int n_in,
                              void* d_out, int out_size) {
    const float* x        = (const float*)d_in[0];
    const float* w        = (const float*)d_in[1];
    const float* noise    = (const float*)d_in[2];
    const float* weight   = (const float*)d_in[3];
    const float* affine_w = (const float*)d_in[4];
    const float* affine_b = (const float*)d_in[5];
    const float* bias     = (const float*)d_in[6];
    float* out = (float*)d_out;

    style_kernel<<<B_, CIN_>>>(w, affine_w, affine_b);
    wsq_kernel<<<(COUT_ * CIN_ + 255) / 256, 256>>>(weight);
    demod_kernel<<<B_, COUT_>>>();

    dim3 grid(COUT_ / COT, (H_ / RT) * (W_ / CT), B_); // (8, 32, 8)
    modconv_kernel<<<grid, 256>>>(x, weight, noise, bias, out);
}